// round 2
// baseline (speedup 1.0000x reference)
#include <cuda_runtime.h>
#include <cuda_fp16.h>
#include <cstdint>

#define DINLINE __device__ __forceinline__

static constexpr int Bd = 2048;
static constexpr int Hd = 256;
static constexpr int Td = 512;
static constexpr int MT = 128;                 // batch tile rows
static constexpr int NT = 128;                 // gate-column tile (= 4 gates x 32 h)
static constexpr int NGRP = Bd / MT;           // 16 M-groups
static constexpr int NSLC = (4 * Hd) / NT;     // 8 N-slices
static constexpr int GRID = NGRP * NSLC;       // 128 CTAs
static constexpr int NTHR = 256;               // 8 warps: 4 (M) x 2 (N)

// SMEM layout (dynamic)
static constexpr int SM_BIAS = 0;                      // 128 floats (float4 per hidden unit)
static constexpr int SM_A = 1024;                      // h tile [128 rows][256 k] f16, XOR-swizzled (64KB)
static constexpr int SM_W = SM_A + 65536;              // W tile [128 n][256 k] f16, XOR-swizzled (64KB)
static constexpr int SM_TOTAL = SM_W + 65536;          // 132096 B

// ---------------- device globals (scratch; no allocations) ----------------
__device__ __align__(16) __half g_hbuf[2][Bd * Hd];                  // ping-pong h (fp16)
__device__ __align__(1024) unsigned char g_Wimg[2][NSLC][65536];     // [W_ih, W_ih+W_hh] smem images
__device__ float g_bias[NSLC][NT];
__device__ unsigned int g_cnt[NGRP];
__device__ int g_gen[NGRP];

// ---------------- helpers ----------------
DINLINE uint32_t smem_u32(const void* p) {
    uint32_t a;
    asm("{ .reg .u64 t; cvta.to.shared.u64 t, %1; cvt.u32.u64 %0, t; }" : "=r"(a) : "l"(p));
    return a;
}
DINLINE void cp16(uint32_t s, const void* g) {
    asm volatile("cp.async.cg.shared.global [%0], [%1], 16;" :: "r"(s), "l"(g));
}
DINLINE void cp_commit() { asm volatile("cp.async.commit_group;" ::: "memory"); }
DINLINE void cp_wait0()  { asm volatile("cp.async.wait_group 0;" ::: "memory"); }

DINLINE void ldsm4(uint32_t* r, uint32_t addr) {
    asm volatile("ldmatrix.sync.aligned.m8n8.x4.shared.b16 {%0,%1,%2,%3}, [%4];"
                 : "=r"(r[0]), "=r"(r[1]), "=r"(r[2]), "=r"(r[3]) : "r"(addr));
}
DINLINE void mma16816(float* c, const uint32_t* a, uint32_t b0, uint32_t b1) {
    asm volatile(
        "mma.sync.aligned.m16n8k16.row.col.f32.f16.f16.f32 "
        "{%0,%1,%2,%3},{%4,%5,%6,%7},{%8,%9},{%0,%1,%2,%3};"
        : "+f"(c[0]), "+f"(c[1]), "+f"(c[2]), "+f"(c[3])
        : "r"(a[0]), "r"(a[1]), "r"(a[2]), "r"(a[3]), "r"(b0), "r"(b1));
}

// EX2+RCP based activations (~1e-6 accurate; avoids tanh.approx's larger abs err)
DINLINE float fsig(float x) {
    float e, r;
    asm("ex2.approx.f32 %0, %1;" : "=f"(e) : "f"(-1.4426950408889634f * x));
    asm("rcp.approx.f32 %0, %1;" : "=f"(r) : "f"(1.0f + e));
    return r;
}
DINLINE float ftanh(float x) {
    float e, r;
    asm("ex2.approx.f32 %0, %1;" : "=f"(e) : "f"(2.8853900817779268f * x));
    asm("rcp.approx.f32 %0, %1;" : "=f"(r) : "f"(1.0f + e));
    return fmaf(-2.0f, r, 1.0f);
}

// Swizzled byte offset within a [rows][256 f16] tile: chunk (16B) XOR low-3 of row
DINLINE uint32_t swz(int row, int chunk) {
    return (uint32_t)(row * 512 + ((chunk ^ (row & 7)) << 4));
}

// ---------------- prologue: permuted/swizzled fp16 W images, bias, x->fp16, barrier reset ----------------
__global__ void prep_kernel(const float* __restrict__ x,
                            const float* __restrict__ Wih, const float* __restrict__ Whh,
                            const float* __restrict__ bih, const float* __restrict__ bhh) {
    int g = blockIdx.x * blockDim.x + threadIdx.x;
    if (g < Bd * Hd) g_hbuf[0][g] = __float2half_rn(x[g]);
    if (g < 2 * NSLC * NT * Hd) {  // 524288 entries
        int set = g >> 18;
        int r = g & 262143;
        int j = r >> 15;
        int n = (r >> 8) & 127;
        int k = r & 255;
        int gate = n & 3, hl = n >> 2;
        int row = gate * Hd + j * 32 + hl;            // original W row in (4H,H)
        float w = Wih[row * Hd + k];
        if (set) w += Whh[row * Hd + k];
        uint32_t byte = (uint32_t)(n * 512 + (((k >> 3) ^ (n & 7)) << 4) + (k & 7) * 2);
        *reinterpret_cast<__half*>(&g_Wimg[set][j][byte]) = __float2half_rn(w);
    }
    if (g < NSLC * NT) {
        int j = g >> 7, n = g & 127;
        int gate = n & 3, hl = n >> 2;
        int row = gate * Hd + j * 32 + hl;
        g_bias[j][n] = bih[row] + bhh[row];
    }
    if (g < NGRP) { g_cnt[g] = 0; g_gen[g] = 0; }
}

// ---------------- main persistent kernel ----------------
__global__ void __launch_bounds__(NTHR, 1) lstm_kernel(float* __restrict__ out) {
    extern __shared__ __align__(1024) char smem[];
    const uint32_t sb = smem_u32(smem);
    const int tid = threadIdx.x, wid = tid >> 5, lane = tid & 31;
    const int cta = blockIdx.x, mg = cta >> 3, j = cta & 7;
    const int wm = wid >> 1, wn = wid & 1;    // warp tile: rows wm*32, cols wn*64

    if (tid < 32)
        reinterpret_cast<float4*>(smem + SM_BIAS)[tid] = reinterpret_cast<const float4*>(g_bias[j])[tid];
    {   // load W_ih image (used only at t=0)
        const unsigned char* src = g_Wimg[0][j];
        #pragma unroll
        for (int i = 0; i < 16; i++) { int q = tid + NTHR * i; cp16(sb + SM_W + q * 16, src + q * 16); }
        cp_commit();
    }
    cp_wait0();
    __syncthreads();

    // ldmatrix per-lane address bases
    // A (x4): m0 rows0-7/klo, m1 rows8-15/klo, m2 rows0-7/khi, m3 rows8-15/khi
    const int a_row_off = (lane & 7) + (((lane >> 3) & 1) << 3);
    const int a_ch_off  = (lane >> 4) & 1;
    uint32_t a_base[2]; int a_rsw[2];
    #pragma unroll
    for (int mt = 0; mt < 2; mt++) {
        int row = wm * 32 + mt * 16 + a_row_off;
        a_base[mt] = sb + SM_A + row * 512;
        a_rsw[mt] = row & 7;
    }
    // B (x4 covers 2 n8-tiles): m0 nt/klo, m1 nt/khi, m2 nt+1/klo, m3 nt+1/khi
    const int b_ch_off = (lane >> 3) & 1;
    uint32_t b_base[4]; int b_rsw[4];
    #pragma unroll
    for (int np = 0; np < 4; np++) {
        int nrow = wn * 64 + np * 16 + (lane & 7) + (((lane >> 4) & 1) << 3);
        b_base[np] = sb + SM_W + nrow * 512;
        b_rsw[np] = nrow & 7;
    }

    // epilogue geometry
    const bool ev = ((lane & 1) == 0);
    const int r_lane = (lane >> 2) + ((lane & 1) << 3);      // + mt*16 + wm*32
    const int hl_lane = wn * 16 + ((lane >> 1) & 1);          // + nt*2
    const int grow0 = mg * MT + wm * 32 + r_lane;
    const int col0 = j * 32 + hl_lane;
    float* const xhat0 = out + (size_t)grow0 * Hd + col0;
    float* const hf0 = out + (size_t)Td * Bd * Hd + (size_t)grow0 * Hd + col0;
    __half* const hb0 = &g_hbuf[0][(size_t)grow0 * Hd + col0];
    __half* const hb1 = &g_hbuf[1][(size_t)grow0 * Hd + col0];

    float cst[16];
    #pragma unroll
    for (int i = 0; i < 16; i++) cst[i] = 0.f;

    #pragma unroll 1
    for (int t = 0; t < Td; t++) {
        const int cur = t & 1;
        // ---- load h tile [128,256] f16 into swizzled A ----
        const __half* hsrc = g_hbuf[cur] + (size_t)mg * MT * Hd;
        #pragma unroll
        for (int i = 0; i < 16; i++) {
            int q = tid + NTHR * i;
            int m = q >> 5, ch = q & 31;
            cp16(sb + SM_A + swz(m, ch), hsrc + m * Hd + ch * 8);
        }
        cp_commit();
        cp_wait0();
        __syncthreads();

        // ---- MMA: gates[128,128] = A[128,256] @ W[128,256]^T ----
        float acc[64];
        #pragma unroll
        for (int i = 0; i < 64; i++) acc[i] = 0.f;
        #pragma unroll
        for (int kt = 0; kt < 16; kt++) {
            uint32_t af[2][4];
            #pragma unroll
            for (int mt = 0; mt < 2; mt++)
                ldsm4(af[mt], a_base[mt] + (((2 * kt + a_ch_off) ^ a_rsw[mt]) << 4));
            uint32_t bf[4][4];
            #pragma unroll
            for (int np = 0; np < 4; np++)
                ldsm4(bf[np], b_base[np] + (((2 * kt + b_ch_off) ^ b_rsw[np]) << 4));
            #pragma unroll
            for (int mt = 0; mt < 2; mt++)
                #pragma unroll
                for (int nt = 0; nt < 8; nt++)
                    mma16816(&acc[(mt * 8 + nt) * 4], af[mt], bf[nt >> 1][(nt & 1) * 2], bf[nt >> 1][(nt & 1) * 2 + 1]);
        }

        if (t == 0) {   // all warps done reading W_ih -> swap in W_sum
            __syncthreads();
            const unsigned char* src = g_Wimg[1][j];
            #pragma unroll
            for (int i = 0; i < 16; i++) { int q = tid + NTHR * i; cp16(sb + SM_W + q * 16, src + q * 16); }
            cp_commit();   // waited by next iteration's cp_wait0 before its MMA
        }

        // ---- epilogue: shuffle-pair gates, activations, state update, stores ----
        const int oidx = (t == 0) ? 0 : (Td - t);   // x_hat[0]=h0, x_hat[k]=h_{T-k}
        float* xp = out + (size_t)oidx * (Bd * Hd);
        __half* hp = (cur ? hb0 : hb1);
        const float4* bias4 = reinterpret_cast<const float4*>(smem + SM_BIAS);
        #pragma unroll
        for (int mt = 0; mt < 2; mt++) {
            #pragma unroll
            for (int nt = 0; nt < 8; nt++) {
                const int li = mt * 8 + nt;
                float c0 = acc[li * 4 + 0], c1 = acc[li * 4 + 1];
                float c2 = acc[li * 4 + 2], c3 = acc[li * 4 + 3];
                float s0 = ev ? c2 : c0, s1 = ev ? c3 : c1;
                float t0 = __shfl_xor_sync(0xffffffffu, s0, 1);
                float t1 = __shfl_xor_sync(0xffffffffu, s1, 1);
                float ipre = ev ? c0 : t0;
                float fpre = ev ? c1 : t1;
                float gpre = ev ? t0 : c2;
                float opre = ev ? t1 : c3;
                const int hl = hl_lane + nt * 2;
                float4 bb = bias4[hl];
                float iv = fsig(ipre + bb.x);
                float fv = fsig(fpre + bb.y);
                float gv = ftanh(gpre + bb.z);
                float ov = fsig(opre + bb.w);
                float cn = fmaf(fv, cst[li], iv * gv);
                cst[li] = cn;
                float hv = ov * ftanh(cn);
                const int off = mt * 16 * Hd + nt * 2;   // row += mt*16, col += nt*2
                hp[off] = __float2half_rn(hv);
                xp[(size_t)grow0 * Hd + col0 + off] = hv;
                if (t == Td - 1) {
                    hf0[off] = hv;
                    hf0[(size_t)Bd * Hd + off] = cn;
                }
            }
        }
        __syncthreads();   // all stores of this CTA done before release below

        // ---- 8-CTA group barrier (monotonic, acq_rel) ----
        if (tid == 0) {
            unsigned old;
            asm volatile("atom.acq_rel.gpu.global.add.u32 %0, [%1], %2;"
                         : "=r"(old) : "l"(&g_cnt[mg]), "r"(1u) : "memory");
            int target = t + 1;
            if (old == (unsigned)(8 * (t + 1) - 1)) {
                asm volatile("st.release.gpu.global.b32 [%0], %1;" :: "l"(&g_gen[mg]), "r"(target) : "memory");
            } else {
                int v;
                do {
                    asm volatile("ld.acquire.gpu.global.b32 %0, [%1];" : "=r"(v) : "l"(&g_gen[mg]) : "memory");
                    if (v < target) __nanosleep(64);
                } while (v < target);
            }
        }
        __syncthreads();
    }
}

// ---------------- launch ----------------
extern "C" void kernel_launch(void* const* d_in, const int* in_sizes, int n_in,
                              void* d_out, int out_size) {
    const float* x   = (const float*)d_in[0];
    const float* Wih = (const float*)d_in[1];
    const float* Whh = (const float*)d_in[2];
    const float* bih = (const float*)d_in[3];
    const float* bhh = (const float*)d_in[4];
    float* out = (float*)d_out;
    (void)in_sizes; (void)n_in; (void)out_size;

    cudaFuncSetAttribute(lstm_kernel, cudaFuncAttributeMaxDynamicSharedMemorySize, SM_TOTAL);

    prep_kernel<<<2048, 256>>>(x, Wih, Whh, bih, bhh);
    lstm_kernel<<<GRID, NTHR, SM_TOTAL>>>(out);
}